// round 15
// baseline (speedup 1.0000x reference)
#include <cuda_runtime.h>
#include <cstdint>
#include <math.h>

#define B_   256
#define T_   256
#define D_   512
#define H_   512
#define O_   256
#define EPS_ 1e-5f

#define TJ_  64    // j-tile per GEMM CTA
#define TK_  32    // k-tile (double buffered)
#define GT_  256   // GEMM threads per CTA
#define NTILE_ (512 / TK_)

typedef unsigned long long ull;

// ---------------- static device scratch ----------------
__device__ float d_xT  [(size_t)T_ * D_ * B_];   // x transposed: [t][k][i]
__device__ float d_bufA[(size_t)T_ * H_ * B_];   // Z buffers [t][j][i]
__device__ float d_bufB[(size_t)T_ * H_ * B_];   // H buffers [t][j][i]
__device__ ull   d_W0d [512 * 512];              // W0 dup: [k][j] = (w,w)
__device__ ull   d_Wmd [512 * 512];              // Wm dup: [k][j] = (w,w)

// ---------------- packed f32x2 helpers ----------------
__device__ __forceinline__ ull pk2(float x, float y) {
    ull r; asm("mov.b64 %0, {%1, %2};" : "=l"(r) : "f"(x), "f"(y)); return r;
}
__device__ __forceinline__ void upk2(float& x, float& y, ull v) {
    asm("mov.b64 {%0, %1}, %2;" : "=f"(x), "=f"(y) : "l"(v));
}
__device__ __forceinline__ void fma2(ull& d, ull a, ull b) {
    asm("fma.rn.f32x2 %0, %1, %2, %0;" : "+l"(d) : "l"(a), "l"(b));
}
__device__ __forceinline__ void cp_async16(unsigned saddr, const void* gaddr) {
    asm volatile("cp.async.cg.shared.global [%0], [%1], 16;"
                 :: "r"(saddr), "l"(gaddr));
}
#define CP_COMMIT() asm volatile("cp.async.commit_group;")
#define CP_WAIT0()  asm volatile("cp.async.wait_group 0;")
#define CP_WAIT6()  asm volatile("cp.async.wait_group 6;")

// ---------------- transpose x: [B][T][D] -> [T][D][B] ----------------
__global__ void transpose_kernel(const float* __restrict__ x) {
    __shared__ float sm[32][33];
    int t  = blockIdx.x;
    int k0 = blockIdx.y * 32;
    int i0 = blockIdx.z * 32;
    int tx = threadIdx.x, ty = threadIdx.y;
    sm[ty][tx] = x[((size_t)(i0 + ty) * T_ + t) * D_ + (k0 + tx)];
    __syncthreads();
    d_xT[((size_t)t * D_ + (k0 + ty)) * B_ + (i0 + tx)] = sm[tx][ty];
}

// ---------------- W duplication: Wdup[k][j] = (W[j][k], W[j][k]) -------------
__global__ void wdup_kernel(const float* __restrict__ W, ull* __restrict__ Wd) {
    __shared__ float sm[32][33];
    int j0 = blockIdx.x * 32;
    int k0 = blockIdx.y * 32;
    int tx = threadIdx.x, ty = threadIdx.y;
    sm[ty][tx] = W[(size_t)(j0 + ty) * 512 + (k0 + tx)];
    __syncthreads();
    float w = sm[tx][ty];
    Wd[(size_t)(k0 + ty) * 512 + (j0 + tx)] = pk2(w, w);
}

// ---------------- GEMM + fused BN1 (all inputs via cp.async, W pre-dup) ------
// OUT[t][j][i] = BN1_over_i( sum_k W[j][k] * IN[t][k][i] )   (bias cancels in BN)
// grid (T_, H_/TJ_), block 256. Warp jq owns 8 j's; lane ip owns i-pairs
// {ip+32q, q<4} -> warp covers full batch -> BN1 = warp shuffle reduction.
#define X_STAGE   (TK_ * B_ * 4)               // 32KB
#define W_STAGE   (TK_ * TJ_ * 8)              // 16KB
#define GEMM_SMEM (2 * (X_STAGE + W_STAGE))    // 96KB -> 2 CTAs/SM

__global__ void __launch_bounds__(GT_, 2) gemm_bn_kernel(
    const float* __restrict__ IN, const ull* __restrict__ Wd,
    const float* __restrict__ gam, const float* __restrict__ bet,
    float* __restrict__ OUT) {

    extern __shared__ __align__(16) char smraw[];
    const int t   = blockIdx.x;
    const int j0  = blockIdx.y * TJ_;
    const int tid = threadIdx.x;
    const int jq  = tid >> 5;     // warp -> j octet
    const int ip  = tid & 31;     // lane -> i pairs {ip+32q}

    float* Xs[2] = { (float*)smraw, (float*)(smraw + X_STAGE) };
    ull*   Ws[2] = { (ull*)(smraw + 2 * X_STAGE),
                     (ull*)(smraw + 2 * X_STAGE + W_STAGE) };
    unsigned xsa[2] = { (unsigned)__cvta_generic_to_shared(Xs[0]),
                        (unsigned)__cvta_generic_to_shared(Xs[1]) };
    unsigned wsa[2] = { (unsigned)__cvta_generic_to_shared(Ws[0]),
                        (unsigned)__cvta_generic_to_shared(Ws[1]) };

    const float* inT = IN + (size_t)t * 512 * 256;
    const ull* wbase = Wd + j0;   // [k][j] rows of 512 ull

    ull acc[8][4];
    #pragma unroll
    for (int jj = 0; jj < 8; jj++)
        #pragma unroll
        for (int q = 0; q < 4; q++) acc[jj][q] = 0ull;

    // --- preamble: stage tile 0 (X + Wdup) ---
    #pragma unroll
    for (int m = 0; m < 8; m++) {
        int idx = m * GT_ + tid;
        int r = idx >> 6, c = idx & 63;
        cp_async16(xsa[0] + (unsigned)(r * 1024 + c * 16),
                   inT + (size_t)r * 256 + c * 4);
    }
    #pragma unroll
    for (int m = 0; m < 4; m++) {
        int idx = m * GT_ + tid;          // 1024 chunks of 16B
        int r = idx >> 5, c = idx & 31;   // r: k-row, c: 2-ull chunk
        cp_async16(wsa[0] + (unsigned)(r * 512 + c * 16),
                   wbase + (size_t)r * 512 + c * 2);
    }
    CP_COMMIT();
    CP_WAIT0();
    __syncthreads();

    // --- pipelined tile loop ---
    for (int it = 0; it < NTILE_; it++) {
        const int cur = it & 1, nxt = cur ^ 1;
        const int ktn = (it + 1) * TK_;
        if (it + 1 < NTILE_) {
            #pragma unroll
            for (int m = 0; m < 8; m++) {
                int idx = m * GT_ + tid;
                int r = idx >> 6, c = idx & 63;
                cp_async16(xsa[nxt] + (unsigned)(r * 1024 + c * 16),
                           inT + (size_t)(ktn + r) * 256 + c * 4);
            }
            #pragma unroll
            for (int m = 0; m < 4; m++) {
                int idx = m * GT_ + tid;
                int r = idx >> 5, c = idx & 31;
                cp_async16(wsa[nxt] + (unsigned)(r * 512 + c * 16),
                           wbase + (size_t)(ktn + r) * 512 + c * 2);
            }
            CP_COMMIT();
        }

        // compute on cur
        const float* xb = Xs[cur];
        const ull*   wb = Ws[cur] + jq * 8;
        #pragma unroll 4
        for (int k = 0; k < TK_; k++) {
            const float* xr = xb + k * 256;
            ull xv0 = *(const ull*)(xr + 2 * ip);
            ull xv1 = *(const ull*)(xr + 2 * ip + 64);
            ull xv2 = *(const ull*)(xr + 2 * ip + 128);
            ull xv3 = *(const ull*)(xr + 2 * ip + 192);
            const ulonglong2* wk = (const ulonglong2*)(wb + k * TJ_);
            ulonglong2 wa = wk[0], wbb = wk[1], wc = wk[2], wd = wk[3];
            fma2(acc[0][0], xv0, wa.x);  fma2(acc[0][1], xv1, wa.x);
            fma2(acc[0][2], xv2, wa.x);  fma2(acc[0][3], xv3, wa.x);
            fma2(acc[1][0], xv0, wa.y);  fma2(acc[1][1], xv1, wa.y);
            fma2(acc[1][2], xv2, wa.y);  fma2(acc[1][3], xv3, wa.y);
            fma2(acc[2][0], xv0, wbb.x); fma2(acc[2][1], xv1, wbb.x);
            fma2(acc[2][2], xv2, wbb.x); fma2(acc[2][3], xv3, wbb.x);
            fma2(acc[3][0], xv0, wbb.y); fma2(acc[3][1], xv1, wbb.y);
            fma2(acc[3][2], xv2, wbb.y); fma2(acc[3][3], xv3, wbb.y);
            fma2(acc[4][0], xv0, wc.x);  fma2(acc[4][1], xv1, wc.x);
            fma2(acc[4][2], xv2, wc.x);  fma2(acc[4][3], xv3, wc.x);
            fma2(acc[5][0], xv0, wc.y);  fma2(acc[5][1], xv1, wc.y);
            fma2(acc[5][2], xv2, wc.y);  fma2(acc[5][3], xv3, wc.y);
            fma2(acc[6][0], xv0, wd.x);  fma2(acc[6][1], xv1, wd.x);
            fma2(acc[6][2], xv2, wd.x);  fma2(acc[6][3], xv3, wd.x);
            fma2(acc[7][0], xv0, wd.y);  fma2(acc[7][1], xv1, wd.y);
            fma2(acc[7][2], xv2, wd.y);  fma2(acc[7][3], xv3, wd.y);
        }

        if (it + 1 < NTILE_) {
            CP_WAIT0();
            __syncthreads();
        }
    }

    // ---- epilogue: BN1 per j (warp-local stats), store ----
    #pragma unroll
    for (int jj = 0; jj < 8; jj++) {
        int j = j0 + jq * 8 + jj;
        float z[8];
        #pragma unroll
        for (int q = 0; q < 4; q++) {
            float a, b2;
            upk2(a, b2, acc[jj][q]);
            z[2 * q] = a; z[2 * q + 1] = b2;
        }
        float s1 = 0.f, s2 = 0.f;
        #pragma unroll
        for (int q = 0; q < 8; q++) { s1 += z[q]; s2 += z[q] * z[q]; }
        #pragma unroll
        for (int off = 16; off > 0; off >>= 1) {
            s1 += __shfl_xor_sync(0xffffffffu, s1, off);
            s2 += __shfl_xor_sync(0xffffffffu, s2, off);
        }
        float m   = s1 * (1.f / B_);
        float var = s2 * (1.f / B_) - m * m;
        float sc  = rsqrtf(var + EPS_) * gam[j];
        float sh  = bet[j] - m * sc;
        float* op = OUT + ((size_t)t * 512 + j) * 256;
        #pragma unroll
        for (int q = 0; q < 4; q++) {
            float ox = z[2 * q] * sc + sh;
            float oy = z[2 * q + 1] * sc + sh;
            *(ull*)(op + 2 * (ip + 32 * q)) = pk2(ox, oy);
        }
    }
}

// ---------------- sequential state scan: cp.async ring, warp-per-column -----
// h(t) = BN2_over_i( relu(Z[t] + h(t-1) * u) );  OUT[t] = h(t)
__global__ void __launch_bounds__(128) scan_kernel(
    const float* __restrict__ Z, const float* __restrict__ u,
    const float* __restrict__ g2, const float* __restrict__ be2,
    float* __restrict__ OUT) {

    __shared__ __align__(16) float ring[4][8][256];   // [warp][stage][i] 32KB

    const int tid  = threadIdx.x;
    const int w    = tid >> 5;
    const int lane = tid & 31;
    const int j    = blockIdx.x * 4 + w;
    const size_t base = (size_t)j * 256 + 8 * lane;
    const size_t tstr = (size_t)512 * 256;

    const float* zsrc = Z + base;
    float* hdst = OUT + base;
    float* myring = &ring[w][0][lane * 8];
    const unsigned rbase = (unsigned)__cvta_generic_to_shared(myring);

    const float uv = u[j], gv = g2[j], bv = be2[j];
    float h[8];
    #pragma unroll
    for (int q = 0; q < 8; q++) h[q] = 0.f;

    // preload stages 0..6 (one commit group per stage)
    #pragma unroll
    for (int s = 0; s < 7; s++) {
        cp_async16(rbase + (unsigned)(s * 1024),      zsrc + (size_t)s * tstr);
        cp_async16(rbase + (unsigned)(s * 1024) + 16, zsrc + (size_t)s * tstr + 4);
        CP_COMMIT();
    }

    for (int t = 0; t < T_; t++) {
        CP_WAIT6();    // stage t resident (own data; no cross-lane use)
        const float* zr = myring + (t & 7) * 256;
        float4 z0 = *(const float4*)(zr);
        float4 z1 = *(const float4*)(zr + 4);

        int tp = t + 7;
        if (tp < T_) {
            cp_async16(rbase + (unsigned)((tp & 7) * 1024),
                       zsrc + (size_t)tp * tstr);
            cp_async16(rbase + (unsigned)((tp & 7) * 1024) + 16,
                       zsrc + (size_t)tp * tstr + 4);
        }
        CP_COMMIT();

        float y[8];
        y[0] = fmaxf(fmaf(h[0], uv, z0.x), 0.f);
        y[1] = fmaxf(fmaf(h[1], uv, z0.y), 0.f);
        y[2] = fmaxf(fmaf(h[2], uv, z0.z), 0.f);
        y[3] = fmaxf(fmaf(h[3], uv, z0.w), 0.f);
        y[4] = fmaxf(fmaf(h[4], uv, z1.x), 0.f);
        y[5] = fmaxf(fmaf(h[5], uv, z1.y), 0.f);
        y[6] = fmaxf(fmaf(h[6], uv, z1.z), 0.f);
        y[7] = fmaxf(fmaf(h[7], uv, z1.w), 0.f);

        float s1 = 0.f, s2 = 0.f;
        #pragma unroll
        for (int q = 0; q < 8; q++) { s1 += y[q]; s2 += y[q] * y[q]; }
        #pragma unroll
        for (int off = 16; off > 0; off >>= 1) {
            s1 += __shfl_xor_sync(0xffffffffu, s1, off);
            s2 += __shfl_xor_sync(0xffffffffu, s2, off);
        }
        float m   = s1 * (1.f / B_);
        float var = s2 * (1.f / B_) - m * m;
        float sc  = rsqrtf(var + EPS_) * gv;
        float sh  = bv - m * sc;
        #pragma unroll
        for (int q = 0; q < 8; q++) h[q] = y[q] * sc + sh;

        float* op = hdst + (size_t)t * tstr;
        *(float4*)(op)     = make_float4(h[0], h[1], h[2], h[3]);
        *(float4*)(op + 4) = make_float4(h[4], h[5], h[6], h[7]);
    }
}

// ---------------- head: logits + log_softmax ----------------
__global__ void __launch_bounds__(256) head_kernel(
    const float* __restrict__ HM,
    const float* __restrict__ Wfc, const float* __restrict__ bfc,
    float* __restrict__ out) {

    __shared__ float hrow[H_];
    __shared__ float shd[8];

    const int r   = blockIdx.x;
    const int tid = threadIdx.x;

    hrow[tid]       = HM[(size_t)tid * 256 + r];
    hrow[tid + 256] = HM[(size_t)(tid + 256) * 256 + r];
    __syncthreads();

    float acc = bfc[tid];
    const float4* wrow = (const float4*)(Wfc + (size_t)tid * H_);
    #pragma unroll 4
    for (int j4 = 0; j4 < H_ / 4; j4++) {
        float4 w = wrow[j4];
        acc = fmaf(hrow[4 * j4 + 0], w.x, acc);
        acc = fmaf(hrow[4 * j4 + 1], w.y, acc);
        acc = fmaf(hrow[4 * j4 + 2], w.z, acc);
        acc = fmaf(hrow[4 * j4 + 3], w.w, acc);
    }

    float v = acc;
    #pragma unroll
    for (int off = 16; off > 0; off >>= 1)
        v = fmaxf(v, __shfl_xor_sync(0xffffffffu, v, off));
    if ((tid & 31) == 0) shd[tid >> 5] = v;
    __syncthreads();
    float mx = shd[0];
    #pragma unroll
    for (int w = 1; w < 8; w++) mx = fmaxf(mx, shd[w]);
    __syncthreads();

    float e = expf(acc - mx);
    float sv = e;
    #pragma unroll
    for (int off = 16; off > 0; off >>= 1)
        sv += __shfl_xor_sync(0xffffffffu, sv, off);
    if ((tid & 31) == 0) shd[tid >> 5] = sv;
    __syncthreads();
    float se = 0.f;
    #pragma unroll
    for (int w = 0; w < 8; w++) se += shd[w];

    out[(size_t)r * O_ + tid] = acc - mx - logf(se);
}

// ---------------- harness entry ----------------
extern "C" void kernel_launch(void* const* d_in, const int* in_sizes, int n_in,
                              void* d_out, int out_size) {
    (void)in_sizes; (void)n_in; (void)out_size;
    const float* x    = (const float*)d_in[0];
    const float* W0   = (const float*)d_in[1];
    const float* u0   = (const float*)d_in[3];
    const float* g10  = (const float*)d_in[4];
    const float* be10 = (const float*)d_in[5];
    const float* g20  = (const float*)d_in[6];
    const float* be20 = (const float*)d_in[7];
    const float* Wm   = (const float*)d_in[8];
    const float* um   = (const float*)d_in[10];
    const float* g1m  = (const float*)d_in[11];
    const float* be1m = (const float*)d_in[12];
    const float* g2m  = (const float*)d_in[13];
    const float* be2m = (const float*)d_in[14];
    const float* Wfc  = (const float*)d_in[15];
    const float* bfc  = (const float*)d_in[16];
    float* out = (float*)d_out;

    static int attr_set = 0;
    if (!attr_set) {
        cudaFuncSetAttribute(gemm_bn_kernel,
                             cudaFuncAttributeMaxDynamicSharedMemorySize, GEMM_SMEM);
        attr_set = 1;
    }

    float* bufA;  cudaGetSymbolAddress((void**)&bufA, d_bufA);
    float* bufB;  cudaGetSymbolAddress((void**)&bufB, d_bufB);
    float* xT;    cudaGetSymbolAddress((void**)&xT,   d_xT);
    ull*   W0d;   cudaGetSymbolAddress((void**)&W0d,  d_W0d);
    ull*   Wmd;   cudaGetSymbolAddress((void**)&Wmd,  d_Wmd);

    transpose_kernel<<<dim3(T_, D_ / 32, B_ / 32), dim3(32, 32)>>>(x);
    wdup_kernel<<<dim3(16, 16), dim3(32, 32)>>>(W0, W0d);
    wdup_kernel<<<dim3(16, 16), dim3(32, 32)>>>(Wm, Wmd);

    gemm_bn_kernel<<<dim3(T_, H_ / TJ_), GT_, GEMM_SMEM>>>(xT, W0d, g10, be10, bufA);
    scan_kernel<<<128, 128>>>(bufA, u0, g20, be20, bufB);
    gemm_bn_kernel<<<dim3(T_, H_ / TJ_), GT_, GEMM_SMEM>>>(bufB, Wmd, g1m, be1m, bufA);
    scan_kernel<<<128, 128>>>(bufA, um, g2m, be2m, bufB);
    gemm_bn_kernel<<<dim3(T_, H_ / TJ_), GT_, GEMM_SMEM>>>(bufB, Wmd, g1m, be1m, bufA);
    scan_kernel<<<128, 128>>>(bufA, um, g2m, be2m, bufB);
    head_kernel<<<O_, 256>>>(bufB + (size_t)(T_ - 1) * H_ * B_, Wfc, bfc, out);
}

// round 16
// speedup vs baseline: 1.0653x; 1.0653x over previous
#include <cuda_runtime.h>
#include <cstdint>
#include <math.h>

#define B_   256
#define T_   256
#define D_   512
#define H_   512
#define O_   256
#define EPS_ 1e-5f

#define TJ_  64    // j-tile per GEMM CTA
#define TK_  32    // k-tile (double buffered)
#define GT_  256   // GEMM threads per CTA
#define NTILE_ (512 / TK_)

typedef unsigned long long ull;

// ---------------- static device scratch ----------------
__device__ float d_xT  [(size_t)T_ * D_ * B_];   // x transposed: [t][k][i]
__device__ float d_bufA[(size_t)T_ * H_ * B_];   // Z buffers [t][j][i]
__device__ float d_bufB[(size_t)T_ * H_ * B_];   // H buffers [t][j][i]
__device__ float d_Wt0 [512 * 512];              // W0 transposed: [k][j]
__device__ float d_Wtm [512 * 512];              // Wm transposed: [k][j]

// ---------------- packed f32x2 helpers ----------------
__device__ __forceinline__ ull pk2(float x, float y) {
    ull r; asm("mov.b64 %0, {%1, %2};" : "=l"(r) : "f"(x), "f"(y)); return r;
}
__device__ __forceinline__ void upk2(float& x, float& y, ull v) {
    asm("mov.b64 {%0, %1}, %2;" : "=f"(x), "=f"(y) : "l"(v));
}
__device__ __forceinline__ void fma2(ull& d, ull a, ull b) {
    asm("fma.rn.f32x2 %0, %1, %2, %0;" : "+l"(d) : "l"(a), "l"(b));
}
__device__ __forceinline__ void cp_async16(unsigned saddr, const void* gaddr) {
    asm volatile("cp.async.cg.shared.global [%0], [%1], 16;"
                 :: "r"(saddr), "l"(gaddr));
}
#define CP_COMMIT() asm volatile("cp.async.commit_group;")
#define CP_WAIT0()  asm volatile("cp.async.wait_group 0;")
#define CP_WAIT6()  asm volatile("cp.async.wait_group 6;")

// ---------------- transpose x: [B][T][D] -> [T][D][B] ----------------
__global__ void transpose_kernel(const float* __restrict__ x) {
    __shared__ float sm[32][33];
    int t  = blockIdx.x;
    int k0 = blockIdx.y * 32;
    int i0 = blockIdx.z * 32;
    int tx = threadIdx.x, ty = threadIdx.y;
    sm[ty][tx] = x[((size_t)(i0 + ty) * T_ + t) * D_ + (k0 + tx)];
    __syncthreads();
    d_xT[((size_t)t * D_ + (k0 + ty)) * B_ + (i0 + tx)] = sm[tx][ty];
}

// ---------------- W transpose: Wt[k][j] = W[j][k] ----------------
__global__ void wtrans_kernel(const float* __restrict__ W, float* __restrict__ Wt) {
    __shared__ float sm[32][33];
    int j0 = blockIdx.x * 32;
    int k0 = blockIdx.y * 32;
    int tx = threadIdx.x, ty = threadIdx.y;
    sm[ty][tx] = W[(size_t)(j0 + ty) * 512 + (k0 + tx)];
    __syncthreads();
    Wt[(size_t)(k0 + ty) * 512 + (j0 + tx)] = sm[tx][ty];
}

// ---------------- GEMM + fused BN1 (j-paired FFMA2 lanes) -------------------
// OUT[t][j][i] = BN1_over_i( sum_k W[j][k] * IN[t][k][i] )   (bias cancels in BN)
// grid (T_, H_/TJ_), block 256. Warp jq owns j's [jq*8, jq*8+8) (4 j-pairs);
// lane ip owns i = 8*ip .. 8*ip+7  -> warp covers full batch for its j's,
// so BN1 = warp shuffle reduction. W pairs come free from Wt via LDS.64.
#define X_STAGE   (TK_ * B_ * 4)               // 32KB
#define W_STAGE   (TK_ * TJ_ * 4)              // 8KB
#define GEMM_SMEM (2 * (X_STAGE + W_STAGE))    // 80KB -> 2 CTAs/SM

__global__ void __launch_bounds__(GT_, 2) gemm_bn_kernel(
    const float* __restrict__ IN, const float* __restrict__ Wt,
    const float* __restrict__ gam, const float* __restrict__ bet,
    float* __restrict__ OUT) {

    extern __shared__ __align__(16) char smraw[];
    const int t   = blockIdx.x;
    const int j0  = blockIdx.y * TJ_;
    const int tid = threadIdx.x;
    const int jq  = tid >> 5;     // warp -> j octet (4 pairs)
    const int ip  = tid & 31;     // lane -> i's {8*ip..8*ip+7}

    float* Xs[2] = { (float*)smraw, (float*)(smraw + X_STAGE) };
    float* Ws[2] = { (float*)(smraw + 2 * X_STAGE),
                     (float*)(smraw + 2 * X_STAGE + W_STAGE) };
    unsigned xsa[2] = { (unsigned)__cvta_generic_to_shared(Xs[0]),
                        (unsigned)__cvta_generic_to_shared(Xs[1]) };
    unsigned wsa[2] = { (unsigned)__cvta_generic_to_shared(Ws[0]),
                        (unsigned)__cvta_generic_to_shared(Ws[1]) };

    const float* inT = IN + (size_t)t * 512 * 256;
    const float* wbase = Wt + j0;   // rows k of 512 floats

    ull acc[4][8];   // [j-pair][i-sub]
    #pragma unroll
    for (int p = 0; p < 4; p++)
        #pragma unroll
        for (int q = 0; q < 8; q++) acc[p][q] = 0ull;

    // --- preamble: stage tile 0 (X + Wt) ---
    #pragma unroll
    for (int m = 0; m < 8; m++) {
        int idx = m * GT_ + tid;
        int r = idx >> 6, c = idx & 63;
        cp_async16(xsa[0] + (unsigned)(r * 1024 + c * 16),
                   inT + (size_t)r * 256 + c * 4);
    }
    #pragma unroll
    for (int m = 0; m < 2; m++) {
        int idx = m * GT_ + tid;          // 512 chunks of 16B
        int r = idx >> 4, c = idx & 15;   // r: k-row (32), c: 16B chunk (16)
        cp_async16(wsa[0] + (unsigned)(r * 256 + c * 16),
                   wbase + (size_t)r * 512 + c * 4);
    }
    CP_COMMIT();
    CP_WAIT0();
    __syncthreads();

    // --- pipelined tile loop ---
    for (int it = 0; it < NTILE_; it++) {
        const int cur = it & 1, nxt = cur ^ 1;
        const int ktn = (it + 1) * TK_;
        if (it + 1 < NTILE_) {
            #pragma unroll
            for (int m = 0; m < 8; m++) {
                int idx = m * GT_ + tid;
                int r = idx >> 6, c = idx & 63;
                cp_async16(xsa[nxt] + (unsigned)(r * 1024 + c * 16),
                           inT + (size_t)(ktn + r) * 256 + c * 4);
            }
            #pragma unroll
            for (int m = 0; m < 2; m++) {
                int idx = m * GT_ + tid;
                int r = idx >> 4, c = idx & 15;
                cp_async16(wsa[nxt] + (unsigned)(r * 256 + c * 16),
                           wbase + (size_t)(ktn + r) * 512 + c * 4);
            }
            CP_COMMIT();
        }

        // compute on cur
        const float* xb = Xs[cur] + 8 * ip;
        const float* wb = Ws[cur] + jq * 8;
        #pragma unroll 4
        for (int k = 0; k < TK_; k++) {
            const float* xr = xb + k * 256;
            float4 xq0 = *(const float4*)(xr);
            float4 xq1 = *(const float4*)(xr + 4);
            ull xd0 = pk2(xq0.x, xq0.x);
            ull xd1 = pk2(xq0.y, xq0.y);
            ull xd2 = pk2(xq0.z, xq0.z);
            ull xd3 = pk2(xq0.w, xq0.w);
            ull xd4 = pk2(xq1.x, xq1.x);
            ull xd5 = pk2(xq1.y, xq1.y);
            ull xd6 = pk2(xq1.z, xq1.z);
            ull xd7 = pk2(xq1.w, xq1.w);
            const float* wk = wb + k * 64;
            ull wp0 = *(const ull*)(wk);       // (w_j0, w_j0+1) broadcast
            ull wp1 = *(const ull*)(wk + 2);
            ull wp2 = *(const ull*)(wk + 4);
            ull wp3 = *(const ull*)(wk + 6);
            fma2(acc[0][0], xd0, wp0); fma2(acc[0][1], xd1, wp0);
            fma2(acc[0][2], xd2, wp0); fma2(acc[0][3], xd3, wp0);
            fma2(acc[0][4], xd4, wp0); fma2(acc[0][5], xd5, wp0);
            fma2(acc[0][6], xd6, wp0); fma2(acc[0][7], xd7, wp0);
            fma2(acc[1][0], xd0, wp1); fma2(acc[1][1], xd1, wp1);
            fma2(acc[1][2], xd2, wp1); fma2(acc[1][3], xd3, wp1);
            fma2(acc[1][4], xd4, wp1); fma2(acc[1][5], xd5, wp1);
            fma2(acc[1][6], xd6, wp1); fma2(acc[1][7], xd7, wp1);
            fma2(acc[2][0], xd0, wp2); fma2(acc[2][1], xd1, wp2);
            fma2(acc[2][2], xd2, wp2); fma2(acc[2][3], xd3, wp2);
            fma2(acc[2][4], xd4, wp2); fma2(acc[2][5], xd5, wp2);
            fma2(acc[2][6], xd6, wp2); fma2(acc[2][7], xd7, wp2);
            fma2(acc[3][0], xd0, wp3); fma2(acc[3][1], xd1, wp3);
            fma2(acc[3][2], xd2, wp3); fma2(acc[3][3], xd3, wp3);
            fma2(acc[3][4], xd4, wp3); fma2(acc[3][5], xd5, wp3);
            fma2(acc[3][6], xd6, wp3); fma2(acc[3][7], xd7, wp3);
        }

        if (it + 1 < NTILE_) {
            CP_WAIT0();
            __syncthreads();
        }
    }

    // ---- epilogue: BN1 per j (warp-local stats over full batch), store ----
    #pragma unroll
    for (int p = 0; p < 4; p++) {
        int je = j0 + jq * 8 + 2 * p;      // even j (lane-x), odd j = je+1 (lane-y)
        float zx[8], zy[8];
        #pragma unroll
        for (int q = 0; q < 8; q++) upk2(zx[q], zy[q], acc[p][q]);

        float s1x = 0.f, s2x = 0.f, s1y = 0.f, s2y = 0.f;
        #pragma unroll
        for (int q = 0; q < 8; q++) {
            s1x += zx[q]; s2x += zx[q] * zx[q];
            s1y += zy[q]; s2y += zy[q] * zy[q];
        }
        #pragma unroll
        for (int off = 16; off > 0; off >>= 1) {
            s1x += __shfl_xor_sync(0xffffffffu, s1x, off);
            s2x += __shfl_xor_sync(0xffffffffu, s2x, off);
            s1y += __shfl_xor_sync(0xffffffffu, s1y, off);
            s2y += __shfl_xor_sync(0xffffffffu, s2y, off);
        }
        float mx  = s1x * (1.f / B_);
        float vx  = s2x * (1.f / B_) - mx * mx;
        float scx = rsqrtf(vx + EPS_) * gam[je];
        float shx = bet[je] - mx * scx;
        float my  = s1y * (1.f / B_);
        float vy  = s2y * (1.f / B_) - my * my;
        float scy = rsqrtf(vy + EPS_) * gam[je + 1];
        float shy = bet[je + 1] - my * scy;

        float* opx = OUT + ((size_t)t * 512 + je) * 256 + 8 * ip;
        float* opy = opx + 256;
        *(float4*)(opx)     = make_float4(zx[0] * scx + shx, zx[1] * scx + shx,
                                          zx[2] * scx + shx, zx[3] * scx + shx);
        *(float4*)(opx + 4) = make_float4(zx[4] * scx + shx, zx[5] * scx + shx,
                                          zx[6] * scx + shx, zx[7] * scx + shx);
        *(float4*)(opy)     = make_float4(zy[0] * scy + shy, zy[1] * scy + shy,
                                          zy[2] * scy + shy, zy[3] * scy + shy);
        *(float4*)(opy + 4) = make_float4(zy[4] * scy + shy, zy[5] * scy + shy,
                                          zy[6] * scy + shy, zy[7] * scy + shy);
    }
}

// ---------------- sequential state scan: cp.async ring, warp-per-column -----
// h(t) = BN2_over_i( relu(Z[t] + h(t-1) * u) );  OUT[t] = h(t)
__global__ void __launch_bounds__(128) scan_kernel(
    const float* __restrict__ Z, const float* __restrict__ u,
    const float* __restrict__ g2, const float* __restrict__ be2,
    float* __restrict__ OUT) {

    __shared__ __align__(16) float ring[4][8][256];   // [warp][stage][i] 32KB

    const int tid  = threadIdx.x;
    const int w    = tid >> 5;
    const int lane = tid & 31;
    const int j    = blockIdx.x * 4 + w;
    const size_t base = (size_t)j * 256 + 8 * lane;
    const size_t tstr = (size_t)512 * 256;

    const float* zsrc = Z + base;
    float* hdst = OUT + base;
    float* myring = &ring[w][0][lane * 8];
    const unsigned rbase = (unsigned)__cvta_generic_to_shared(myring);

    const float uv = u[j], gv = g2[j], bv = be2[j];
    float h[8];
    #pragma unroll
    for (int q = 0; q < 8; q++) h[q] = 0.f;

    // preload stages 0..6 (one commit group per stage)
    #pragma unroll
    for (int s = 0; s < 7; s++) {
        cp_async16(rbase + (unsigned)(s * 1024),      zsrc + (size_t)s * tstr);
        cp_async16(rbase + (unsigned)(s * 1024) + 16, zsrc + (size_t)s * tstr + 4);
        CP_COMMIT();
    }

    for (int t = 0; t < T_; t++) {
        CP_WAIT6();    // stage t resident (own data; no cross-lane use)
        const float* zr = myring + (t & 7) * 256;
        float4 z0 = *(const float4*)(zr);
        float4 z1 = *(const float4*)(zr + 4);

        int tp = t + 7;
        if (tp < T_) {
            cp_async16(rbase + (unsigned)((tp & 7) * 1024),
                       zsrc + (size_t)tp * tstr);
            cp_async16(rbase + (unsigned)((tp & 7) * 1024) + 16,
                       zsrc + (size_t)tp * tstr + 4);
        }
        CP_COMMIT();

        float y[8];
        y[0] = fmaxf(fmaf(h[0], uv, z0.x), 0.f);
        y[1] = fmaxf(fmaf(h[1], uv, z0.y), 0.f);
        y[2] = fmaxf(fmaf(h[2], uv, z0.z), 0.f);
        y[3] = fmaxf(fmaf(h[3], uv, z0.w), 0.f);
        y[4] = fmaxf(fmaf(h[4], uv, z1.x), 0.f);
        y[5] = fmaxf(fmaf(h[5], uv, z1.y), 0.f);
        y[6] = fmaxf(fmaf(h[6], uv, z1.z), 0.f);
        y[7] = fmaxf(fmaf(h[7], uv, z1.w), 0.f);

        float s1 = 0.f, s2 = 0.f;
        #pragma unroll
        for (int q = 0; q < 8; q++) { s1 += y[q]; s2 += y[q] * y[q]; }
        #pragma unroll
        for (int off = 16; off > 0; off >>= 1) {
            s1 += __shfl_xor_sync(0xffffffffu, s1, off);
            s2 += __shfl_xor_sync(0xffffffffu, s2, off);
        }
        float m   = s1 * (1.f / B_);
        float var = s2 * (1.f / B_) - m * m;
        float sc  = rsqrtf(var + EPS_) * gv;
        float sh  = bv - m * sc;
        #pragma unroll
        for (int q = 0; q < 8; q++) h[q] = y[q] * sc + sh;

        float* op = hdst + (size_t)t * tstr;
        *(float4*)(op)     = make_float4(h[0], h[1], h[2], h[3]);
        *(float4*)(op + 4) = make_float4(h[4], h[5], h[6], h[7]);
    }
}

// ---------------- head: logits + log_softmax ----------------
__global__ void __launch_bounds__(256) head_kernel(
    const float* __restrict__ HM,
    const float* __restrict__ Wfc, const float* __restrict__ bfc,
    float* __restrict__ out) {

    __shared__ float hrow[H_];
    __shared__ float shd[8];

    const int r   = blockIdx.x;
    const int tid = threadIdx.x;

    hrow[tid]       = HM[(size_t)tid * 256 + r];
    hrow[tid + 256] = HM[(size_t)(tid + 256) * 256 + r];
    __syncthreads();

    float acc = bfc[tid];
    const float4* wrow = (const float4*)(Wfc + (size_t)tid * H_);
    #pragma unroll 4
    for (int j4 = 0; j4 < H_ / 4; j4++) {
        float4 w = wrow[j4];
        acc = fmaf(hrow[4 * j4 + 0], w.x, acc);
        acc = fmaf(hrow[4 * j4 + 1], w.y, acc);
        acc = fmaf(hrow[4 * j4 + 2], w.z, acc);
        acc = fmaf(hrow[4 * j4 + 3], w.w, acc);
    }

    float v = acc;
    #pragma unroll
    for (int off = 16; off > 0; off >>= 1)
        v = fmaxf(v, __shfl_xor_sync(0xffffffffu, v, off));
    if ((tid & 31) == 0) shd[tid >> 5] = v;
    __syncthreads();
    float mx = shd[0];
    #pragma unroll
    for (int w = 1; w < 8; w++) mx = fmaxf(mx, shd[w]);
    __syncthreads();

    float e = expf(acc - mx);
    float sv = e;
    #pragma unroll
    for (int off = 16; off > 0; off >>= 1)
        sv += __shfl_xor_sync(0xffffffffu, sv, off);
    if ((tid & 31) == 0) shd[tid >> 5] = sv;
    __syncthreads();
    float se = 0.f;
    #pragma unroll
    for (int w = 0; w < 8; w++) se += shd[w];

    out[(size_t)r * O_ + tid] = acc - mx - logf(se);
}

// ---------------- harness entry ----------------
extern "C" void kernel_launch(void* const* d_in, const int* in_sizes, int n_in,
                              void* d_out, int out_size) {
    (void)in_sizes; (void)n_in; (void)out_size;
    const float* x    = (const float*)d_in[0];
    const float* W0   = (const float*)d_in[1];
    const float* u0   = (const float*)d_in[3];
    const float* g10  = (const float*)d_in[4];
    const float* be10 = (const float*)d_in[5];
    const float* g20  = (const float*)d_in[6];
    const float* be20 = (const float*)d_in[7];
    const float* Wm   = (const float*)d_in[8];
    const float* um   = (const float*)d_in[10];
    const float* g1m  = (const float*)d_in[11];
    const float* be1m = (const float*)d_in[12];
    const float* g2m  = (const float*)d_in[13];
    const float* be2m = (const float*)d_in[14];
    const float* Wfc  = (const float*)d_in[15];
    const float* bfc  = (const float*)d_in[16];
    float* out = (float*)d_out;

    static int attr_set = 0;
    if (!attr_set) {
        cudaFuncSetAttribute(gemm_bn_kernel,
                             cudaFuncAttributeMaxDynamicSharedMemorySize, GEMM_SMEM);
        attr_set = 1;
    }

    float* bufA;  cudaGetSymbolAddress((void**)&bufA, d_bufA);
    float* bufB;  cudaGetSymbolAddress((void**)&bufB, d_bufB);
    float* xT;    cudaGetSymbolAddress((void**)&xT,   d_xT);
    float* Wt0;   cudaGetSymbolAddress((void**)&Wt0,  d_Wt0);
    float* Wtm;   cudaGetSymbolAddress((void**)&Wtm,  d_Wtm);

    transpose_kernel<<<dim3(T_, D_ / 32, B_ / 32), dim3(32, 32)>>>(x);
    wtrans_kernel<<<dim3(16, 16), dim3(32, 32)>>>(W0, Wt0);
    wtrans_kernel<<<dim3(16, 16), dim3(32, 32)>>>(Wm, Wtm);

    gemm_bn_kernel<<<dim3(T_, H_ / TJ_), GT_, GEMM_SMEM>>>(xT, Wt0, g10, be10, bufA);
    scan_kernel<<<128, 128>>>(bufA, u0, g20, be20, bufB);
    gemm_bn_kernel<<<dim3(T_, H_ / TJ_), GT_, GEMM_SMEM>>>(bufB, Wtm, g1m, be1m, bufA);
    scan_kernel<<<128, 128>>>(bufA, um, g2m, be2m, bufB);
    gemm_bn_kernel<<<dim3(T_, H_ / TJ_), GT_, GEMM_SMEM>>>(bufB, Wtm, g1m, be1m, bufA);
    scan_kernel<<<128, 128>>>(bufA, um, g2m, be2m, bufB);
    head_kernel<<<O_, 256>>>(bufB + (size_t)(T_ - 1) * H_ * B_, Wfc, bfc, out);
}